// round 3
// baseline (speedup 1.0000x reference)
#include <cuda_runtime.h>
#include <math.h>

#define B_  2
#define T_  1024
#define D_  1024
#define H_  16
#define HD_ 64
#define L_  8
#define FF_ 4096
#define V_  32000
#define EPS_ 1e-5f
#define SCALE_ 0.125f   // 1/sqrt(64)

// ---------------- scratch (no allocs allowed) ----------------
__device__ float g_x [B_*T_*D_];   // residual stream
__device__ float g_h [B_*T_*D_];   // ln output / attn output
__device__ float g_q [B_*T_*D_];
__device__ float g_k [B_*T_*D_];
__device__ float g_v [B_*T_*D_];
__device__ float g_ff[B_*T_*FF_];
__device__ float g_xf[B_*D_];      // final-LN of last token per batch

// ---------------- embedding ----------------
__global__ void embed_kernel(const int* __restrict__ idx,
                             const float* __restrict__ tok,
                             const float* __restrict__ pos) {
    int row = blockIdx.x;              // b*T + t
    int t = row & (T_ - 1);
    int tokid = idx[row];
    const float* te = tok + (size_t)tokid * D_;
    const float* pe = pos + (size_t)t * D_;
    float* out = g_x + (size_t)row * D_;
    for (int i = threadIdx.x; i < D_; i += blockDim.x)
        out[i] = te[i] + pe[i];
}

// ---------------- layernorm ----------------
__device__ __forceinline__ void ln_row(const float* __restrict__ xin,
                                       const float* __restrict__ w,
                                       const float* __restrict__ b,
                                       float* __restrict__ out) {
    __shared__ float sx[D_];
    __shared__ float red[256];
    int tid = threadIdx.x;
    float s = 0.f;
    for (int i = tid; i < D_; i += 256) { float v = xin[i]; sx[i] = v; s += v; }
    red[tid] = s; __syncthreads();
    for (int off = 128; off > 0; off >>= 1) {
        if (tid < off) red[tid] += red[tid + off];
        __syncthreads();
    }
    float mean = red[0] * (1.f / D_);
    __syncthreads();
    float s2 = 0.f;
    for (int i = tid; i < D_; i += 256) { float d = sx[i] - mean; s2 += d * d; }
    red[tid] = s2; __syncthreads();
    for (int off = 128; off > 0; off >>= 1) {
        if (tid < off) red[tid] += red[tid + off];
        __syncthreads();
    }
    float rstd = rsqrtf(red[0] * (1.f / D_) + EPS_);
    for (int i = tid; i < D_; i += 256)
        out[i] = (sx[i] - mean) * rstd * w[i] + b[i];
}

__global__ void ln_kernel(const float* __restrict__ in,
                          const float* __restrict__ w,
                          const float* __restrict__ b,
                          float* __restrict__ out) {
    ln_row(in + (size_t)blockIdx.x * D_, w, b, out + (size_t)blockIdx.x * D_);
}

__global__ void lnf_kernel(const float* __restrict__ w, const float* __restrict__ b) {
    // one block per batch row, take last token
    const float* in = g_x + ((size_t)blockIdx.x * T_ + (T_ - 1)) * D_;
    ln_row(in, w, b, g_xf + (size_t)blockIdx.x * D_);
}

// ---------------- SGEMM 128x128x8, TM=TN=8, 256 threads ----------------
#define BM 128
#define BN 128
#define BK 8
#define TM 8
#define TN 8

__device__ __forceinline__ void sgemm_core(
    const float* __restrict__ A, const float* __restrict__ Bw,
    const float* __restrict__ bias, const float* __restrict__ res,
    float* __restrict__ C, int N, int K, int doRelu, int addRes,
    int bx, int by)
{
    __shared__ float As[BK][BM];
    __shared__ float Bs[BK][BN];
    const int tid = threadIdx.x;
    const int ty = tid >> 4;        // 0..15
    const int tx = tid & 15;        // 0..15

    float acc[TM][TN];
    #pragma unroll
    for (int i = 0; i < TM; i++)
        #pragma unroll
        for (int j = 0; j < TN; j++) acc[i][j] = 0.f;

    const int aRow = tid >> 1;            // 0..127
    const int aCol = (tid & 1) * 4;       // 0 or 4
    const int bRow = tid >> 5;            // 0..7
    const int bCol = (tid & 31) * 4;      // 0..124

    const float* Aptr = A + (size_t)(by * BM + aRow) * K + aCol;
    const float* Bptr = Bw + (size_t)bRow * N + (size_t)bx * BN + bCol;

    for (int k0 = 0; k0 < K; k0 += BK) {
        float4 a = *(const float4*)(Aptr + k0);
        As[aCol + 0][aRow] = a.x;
        As[aCol + 1][aRow] = a.y;
        As[aCol + 2][aRow] = a.z;
        As[aCol + 3][aRow] = a.w;
        float4 bv = *(const float4*)(Bptr + (size_t)k0 * N);
        *(float4*)&Bs[bRow][bCol] = bv;
        __syncthreads();

        #pragma unroll
        for (int k = 0; k < BK; k++) {
            float4 ra0 = *(const float4*)&As[k][ty * TM];
            float4 ra1 = *(const float4*)&As[k][ty * TM + 4];
            float4 rb0 = *(const float4*)&Bs[k][tx * TN];
            float4 rb1 = *(const float4*)&Bs[k][tx * TN + 4];
            float ra[TM] = {ra0.x, ra0.y, ra0.z, ra0.w, ra1.x, ra1.y, ra1.z, ra1.w};
            float rb[TN] = {rb0.x, rb0.y, rb0.z, rb0.w, rb1.x, rb1.y, rb1.z, rb1.w};
            #pragma unroll
            for (int i = 0; i < TM; i++)
                #pragma unroll
                for (int j = 0; j < TN; j++)
                    acc[i][j] += ra[i] * rb[j];
        }
        __syncthreads();
    }

    // epilogue: C = [relu](acc + bias) [+ res]
    #pragma unroll
    for (int i = 0; i < TM; i++) {
        int row = by * BM + ty * TM + i;
        #pragma unroll
        for (int j = 0; j < TN; j += 4) {
            int col = bx * BN + tx * TN + j;
            float4 c;
            c.x = acc[i][j + 0] + bias[col + 0];
            c.y = acc[i][j + 1] + bias[col + 1];
            c.z = acc[i][j + 2] + bias[col + 2];
            c.w = acc[i][j + 3] + bias[col + 3];
            if (doRelu) {
                c.x = fmaxf(c.x, 0.f); c.y = fmaxf(c.y, 0.f);
                c.z = fmaxf(c.z, 0.f); c.w = fmaxf(c.w, 0.f);
            }
            if (addRes) {
                float4 r = *(const float4*)(res + (size_t)row * N + col);
                c.x += r.x; c.y += r.y; c.z += r.z; c.w += r.w;
            }
            *(float4*)(C + (size_t)row * N + col) = c;
        }
    }
}

__global__ __launch_bounds__(256)
void gemm_kernel(const float* __restrict__ A, const float* __restrict__ Bw,
                 const float* __restrict__ bias, const float* __restrict__ res,
                 float* __restrict__ C, int N, int K, int doRelu, int addRes) {
    sgemm_core(A, Bw, bias, res, C, N, K, doRelu, addRes, blockIdx.x, blockIdx.y);
}

__global__ __launch_bounds__(256)
void gemm_qkv_kernel(const float* __restrict__ qw, const float* __restrict__ kw,
                     const float* __restrict__ vw, const float* __restrict__ qb,
                     const float* __restrict__ kb, const float* __restrict__ vb) {
    int z = blockIdx.z;
    const float* Bw   = (z == 0) ? qw : (z == 1) ? kw : vw;
    const float* bias = (z == 0) ? qb : (z == 1) ? kb : vb;
    float* C          = (z == 0) ? g_q : (z == 1) ? g_k : g_v;
    sgemm_core(g_h, Bw, bias, nullptr, C, D_, D_, 0, 0, blockIdx.x, blockIdx.y);
}

// ---------------- flash attention (fp32, warp per query row) ----------------
__global__ __launch_bounds__(256)
void attn_kernel() {
    __shared__ float sK[32][64];
    __shared__ float sV[32][64];
    const int warp = threadIdx.x >> 5;
    const int lane = threadIdx.x & 31;
    const int qrow = blockIdx.x * 8 + warp;
    const int h = blockIdx.y, b = blockIdx.z;
    const size_t base = (size_t)b * T_ * D_ + (size_t)h * HD_;

    const float* Qp = g_q + base + (size_t)qrow * D_;
    float q0 = Qp[lane] * SCALE_;
    float q1 = Qp[lane + 32] * SCALE_;

    float m = -1e30f, l = 0.f, a0 = 0.f, a1 = 0.f;
    const int maxrow = blockIdx.x * 8 + 7;
    const int ntiles = maxrow / 32 + 1;

    for (int t = 0; t < ntiles; t++) {
        for (int i = threadIdx.x; i < 32 * 64; i += 256) {
            int r = i >> 6, c = i & 63;
            size_t g = base + (size_t)(t * 32 + r) * D_ + c;
            sK[r][c] = g_k[g];
            sV[r][c] = g_v[g];
        }
        __syncthreads();
        int kend = min(31, qrow - t * 32);
        for (int j = 0; j <= kend; j++) {
            float s = q0 * sK[j][lane] + q1 * sK[j][lane + 32];
            s += __shfl_xor_sync(0xffffffffu, s, 16);
            s += __shfl_xor_sync(0xffffffffu, s, 8);
            s += __shfl_xor_sync(0xffffffffu, s, 4);
            s += __shfl_xor_sync(0xffffffffu, s, 2);
            s += __shfl_xor_sync(0xffffffffu, s, 1);
            float nm = fmaxf(m, s);
            float corr = __expf(m - nm);
            float p = __expf(s - nm);
            l = l * corr + p;
            a0 = a0 * corr + p * sV[j][lane];
            a1 = a1 * corr + p * sV[j][lane + 32];
            m = nm;
        }
        __syncthreads();
    }
    float inv = 1.f / l;
    g_h[base + (size_t)qrow * D_ + lane]      = a0 * inv;
    g_h[base + (size_t)qrow * D_ + lane + 32] = a1 * inv;
}

// ---------------- head: [B,D] @ [D,V] + b ----------------
__global__ __launch_bounds__(128)
void head_kernel(const float* __restrict__ hw, const float* __restrict__ hb,
                 float* __restrict__ out) {
    __shared__ float sx[2][D_];
    for (int i = threadIdx.x; i < 2 * D_; i += 128)
        sx[i / D_][i % D_] = g_xf[i];
    __syncthreads();
    int v = blockIdx.x * 128 + threadIdx.x;
    float a0 = 0.f, a1 = 0.f;
    #pragma unroll 8
    for (int d = 0; d < D_; d++) {
        float w = hw[(size_t)d * V_ + v];
        a0 += sx[0][d] * w;
        a1 += sx[1][d] * w;
    }
    out[v]      = a0 + hb[v];
    out[V_ + v] = a1 + hb[v];
}

// ---------------- launch ----------------
extern "C" void kernel_launch(void* const* d_in, const int* in_sizes, int n_in,
                              void* d_out, int out_size) {
    const int*   idx  = (const int*)  d_in[0];
    const float* tok  = (const float*)d_in[1];
    const float* pos  = (const float*)d_in[2];
    const float* ln1w = (const float*)d_in[3];
    const float* ln1b = (const float*)d_in[4];
    const float* qw   = (const float*)d_in[5];
    const float* qb   = (const float*)d_in[6];
    const float* kw   = (const float*)d_in[7];
    const float* kb   = (const float*)d_in[8];
    const float* vw   = (const float*)d_in[9];
    const float* vb   = (const float*)d_in[10];
    const float* ow   = (const float*)d_in[11];
    const float* ob   = (const float*)d_in[12];
    const float* ln2w = (const float*)d_in[13];
    const float* ln2b = (const float*)d_in[14];
    const float* f1w  = (const float*)d_in[15];
    const float* f1b  = (const float*)d_in[16];
    const float* f2w  = (const float*)d_in[17];
    const float* f2b  = (const float*)d_in[18];
    const float* lnfw = (const float*)d_in[19];
    const float* lnfb = (const float*)d_in[20];
    const float* hw   = (const float*)d_in[21];
    const float* hb   = (const float*)d_in[22];
    float* out = (float*)d_out;

    float *px, *ph, *pff;
    cudaGetSymbolAddress((void**)&px,  g_x);
    cudaGetSymbolAddress((void**)&ph,  g_h);
    cudaGetSymbolAddress((void**)&pff, g_ff);

    const int ROWS = B_ * T_;   // 2048

    embed_kernel<<<ROWS, 256>>>(idx, tok, pos);

    dim3 gD(D_ / BN, ROWS / BM);          // 8 x 16
    dim3 gQKV(D_ / BN, ROWS / BM, 3);     // 8 x 16 x 3
    dim3 gF1(FF_ / BN, ROWS / BM);        // 32 x 16
    dim3 gAttn(T_ / 8, H_, B_);           // 128 x 16 x 2

    for (int l = 0; l < L_; l++) {
        const size_t wO = (size_t)l * D_ * D_;
        ln_kernel<<<ROWS, 256>>>(px, ln1w + (size_t)l * D_, ln1b + (size_t)l * D_, ph);
        gemm_qkv_kernel<<<gQKV, 256>>>(qw + wO, kw + wO, vw + wO,
                                       qb + (size_t)l * D_, kb + (size_t)l * D_, vb + (size_t)l * D_);
        attn_kernel<<<gAttn, 256>>>();
        gemm_kernel<<<gD, 256>>>(ph, ow + wO, ob + (size_t)l * D_, px, px, D_, D_, 0, 1);
        ln_kernel<<<ROWS, 256>>>(px, ln2w + (size_t)l * D_, ln2b + (size_t)l * D_, ph);
        gemm_kernel<<<gF1, 256>>>(ph, f1w + (size_t)l * D_ * FF_, f1b + (size_t)l * FF_,
                                  nullptr, pff, FF_, D_, 1, 0);
        gemm_kernel<<<gD, 256>>>(pff, f2w + (size_t)l * FF_ * D_, f2b + (size_t)l * D_,
                                 px, px, D_, FF_, 0, 1);
    }

    lnf_kernel<<<B_, 256>>>(lnfw, lnfb);
    head_kernel<<<V_ / 128, 128>>>(hw, hb, out);
}

// round 4
// speedup vs baseline: 1.0005x; 1.0005x over previous
#include <cuda_runtime.h>
#include <math.h>

#define B_  2
#define T_  1024
#define D_  1024
#define H_  16
#define HD_ 64
#define L_  8
#define FF_ 4096
#define V_  32000
#define EPS_ 1e-5f
#define SCALE_ 0.125f   // 1/sqrt(64)

// ---------------- scratch (no allocs allowed) ----------------
__device__ float g_x [B_*T_*D_];   // residual stream
__device__ float g_h [B_*T_*D_];   // ln output / attn output
__device__ float g_q [B_*T_*D_];
__device__ float g_k [B_*T_*D_];
__device__ float g_v [B_*T_*D_];
__device__ float g_ff[B_*T_*FF_];
__device__ float g_xf[B_*D_];      // final-LN of last token per batch

// ---------------- embedding ----------------
__global__ void embed_kernel(const int* __restrict__ idx,
                             const float* __restrict__ tok,
                             const float* __restrict__ pos) {
    int row = blockIdx.x;              // b*T + t
    int t = row & (T_ - 1);
    int tokid = idx[row];
    const float* te = tok + (size_t)tokid * D_;
    const float* pe = pos + (size_t)t * D_;
    float* out = g_x + (size_t)row * D_;
    for (int i = threadIdx.x; i < D_; i += blockDim.x)
        out[i] = te[i] + pe[i];
}

// ---------------- layernorm ----------------
__device__ __forceinline__ void ln_row(const float* __restrict__ xin,
                                       const float* __restrict__ w,
                                       const float* __restrict__ b,
                                       float* __restrict__ out) {
    __shared__ float sx[D_];
    __shared__ float red[256];
    int tid = threadIdx.x;
    float s = 0.f;
    for (int i = tid; i < D_; i += 256) { float v = xin[i]; sx[i] = v; s += v; }
    red[tid] = s; __syncthreads();
    for (int off = 128; off > 0; off >>= 1) {
        if (tid < off) red[tid] += red[tid + off];
        __syncthreads();
    }
    float mean = red[0] * (1.f / D_);
    __syncthreads();
    float s2 = 0.f;
    for (int i = tid; i < D_; i += 256) { float d = sx[i] - mean; s2 += d * d; }
    red[tid] = s2; __syncthreads();
    for (int off = 128; off > 0; off >>= 1) {
        if (tid < off) red[tid] += red[tid + off];
        __syncthreads();
    }
    float rstd = rsqrtf(red[0] * (1.f / D_) + EPS_);
    for (int i = tid; i < D_; i += 256)
        out[i] = (sx[i] - mean) * rstd * w[i] + b[i];
}

__global__ void ln_kernel(const float* __restrict__ in,
                          const float* __restrict__ w,
                          const float* __restrict__ b,
                          float* __restrict__ out) {
    ln_row(in + (size_t)blockIdx.x * D_, w, b, out + (size_t)blockIdx.x * D_);
}

__global__ void lnf_kernel(const float* __restrict__ w, const float* __restrict__ b) {
    // one block per batch row, take last token
    const float* in = g_x + ((size_t)blockIdx.x * T_ + (T_ - 1)) * D_;
    ln_row(in, w, b, g_xf + (size_t)blockIdx.x * D_);
}

// ---------------- SGEMM 128x128x8, TM=TN=8, 256 threads ----------------
#define BM 128
#define BN 128
#define BK 8
#define TM 8
#define TN 8

__device__ __forceinline__ void sgemm_core(
    const float* __restrict__ A, const float* __restrict__ Bw,
    const float* __restrict__ bias, const float* __restrict__ res,
    float* __restrict__ C, int N, int K, int doRelu, int addRes,
    int bx, int by)
{
    __shared__ float As[BK][BM];
    __shared__ float Bs[BK][BN];
    const int tid = threadIdx.x;
    const int ty = tid >> 4;        // 0..15
    const int tx = tid & 15;        // 0..15

    float acc[TM][TN];
    #pragma unroll
    for (int i = 0; i < TM; i++)
        #pragma unroll
        for (int j = 0; j < TN; j++) acc[i][j] = 0.f;

    const int aRow = tid >> 1;            // 0..127
    const int aCol = (tid & 1) * 4;       // 0 or 4
    const int bRow = tid >> 5;            // 0..7
    const int bCol = (tid & 31) * 4;      // 0..124

    const float* Aptr = A + (size_t)(by * BM + aRow) * K + aCol;
    const float* Bptr = Bw + (size_t)bRow * N + (size_t)bx * BN + bCol;

    for (int k0 = 0; k0 < K; k0 += BK) {
        float4 a = *(const float4*)(Aptr + k0);
        As[aCol + 0][aRow] = a.x;
        As[aCol + 1][aRow] = a.y;
        As[aCol + 2][aRow] = a.z;
        As[aCol + 3][aRow] = a.w;
        float4 bv = *(const float4*)(Bptr + (size_t)k0 * N);
        *(float4*)&Bs[bRow][bCol] = bv;
        __syncthreads();

        #pragma unroll
        for (int k = 0; k < BK; k++) {
            float4 ra0 = *(const float4*)&As[k][ty * TM];
            float4 ra1 = *(const float4*)&As[k][ty * TM + 4];
            float4 rb0 = *(const float4*)&Bs[k][tx * TN];
            float4 rb1 = *(const float4*)&Bs[k][tx * TN + 4];
            float ra[TM] = {ra0.x, ra0.y, ra0.z, ra0.w, ra1.x, ra1.y, ra1.z, ra1.w};
            float rb[TN] = {rb0.x, rb0.y, rb0.z, rb0.w, rb1.x, rb1.y, rb1.z, rb1.w};
            #pragma unroll
            for (int i = 0; i < TM; i++)
                #pragma unroll
                for (int j = 0; j < TN; j++)
                    acc[i][j] += ra[i] * rb[j];
        }
        __syncthreads();
    }

    // epilogue: C = [relu](acc + bias) [+ res]
    #pragma unroll
    for (int i = 0; i < TM; i++) {
        int row = by * BM + ty * TM + i;
        #pragma unroll
        for (int j = 0; j < TN; j += 4) {
            int col = bx * BN + tx * TN + j;
            float4 c;
            c.x = acc[i][j + 0] + bias[col + 0];
            c.y = acc[i][j + 1] + bias[col + 1];
            c.z = acc[i][j + 2] + bias[col + 2];
            c.w = acc[i][j + 3] + bias[col + 3];
            if (doRelu) {
                c.x = fmaxf(c.x, 0.f); c.y = fmaxf(c.y, 0.f);
                c.z = fmaxf(c.z, 0.f); c.w = fmaxf(c.w, 0.f);
            }
            if (addRes) {
                float4 r = *(const float4*)(res + (size_t)row * N + col);
                c.x += r.x; c.y += r.y; c.z += r.z; c.w += r.w;
            }
            *(float4*)(C + (size_t)row * N + col) = c;
        }
    }
}

__global__ __launch_bounds__(256)
void gemm_kernel(const float* __restrict__ A, const float* __restrict__ Bw,
                 const float* __restrict__ bias, const float* __restrict__ res,
                 float* __restrict__ C, int N, int K, int doRelu, int addRes) {
    sgemm_core(A, Bw, bias, res, C, N, K, doRelu, addRes, blockIdx.x, blockIdx.y);
}

__global__ __launch_bounds__(256)
void gemm_qkv_kernel(const float* __restrict__ qw, const float* __restrict__ kw,
                     const float* __restrict__ vw, const float* __restrict__ qb,
                     const float* __restrict__ kb, const float* __restrict__ vb) {
    int z = blockIdx.z;
    const float* Bw   = (z == 0) ? qw : (z == 1) ? kw : vw;
    const float* bias = (z == 0) ? qb : (z == 1) ? kb : vb;
    float* C          = (z == 0) ? g_q : (z == 1) ? g_k : g_v;
    sgemm_core(g_h, Bw, bias, nullptr, C, D_, D_, 0, 0, blockIdx.x, blockIdx.y);
}

// ---------------- flash attention (fp32, warp per query row) ----------------
__global__ __launch_bounds__(256)
void attn_kernel() {
    __shared__ float sK[32][64];
    __shared__ float sV[32][64];
    const int warp = threadIdx.x >> 5;
    const int lane = threadIdx.x & 31;
    const int qrow = blockIdx.x * 8 + warp;
    const int h = blockIdx.y, b = blockIdx.z;
    const size_t base = (size_t)b * T_ * D_ + (size_t)h * HD_;

    const float* Qp = g_q + base + (size_t)qrow * D_;
    float q0 = Qp[lane] * SCALE_;
    float q1 = Qp[lane + 32] * SCALE_;

    float m = -1e30f, l = 0.f, a0 = 0.f, a1 = 0.f;
    const int maxrow = blockIdx.x * 8 + 7;
    const int ntiles = maxrow / 32 + 1;

    for (int t = 0; t < ntiles; t++) {
        for (int i = threadIdx.x; i < 32 * 64; i += 256) {
            int r = i >> 6, c = i & 63;
            size_t g = base + (size_t)(t * 32 + r) * D_ + c;
            sK[r][c] = g_k[g];
            sV[r][c] = g_v[g];
        }
        __syncthreads();
        int kend = min(31, qrow - t * 32);
        for (int j = 0; j <= kend; j++) {
            float s = q0 * sK[j][lane] + q1 * sK[j][lane + 32];
            s += __shfl_xor_sync(0xffffffffu, s, 16);
            s += __shfl_xor_sync(0xffffffffu, s, 8);
            s += __shfl_xor_sync(0xffffffffu, s, 4);
            s += __shfl_xor_sync(0xffffffffu, s, 2);
            s += __shfl_xor_sync(0xffffffffu, s, 1);
            float nm = fmaxf(m, s);
            float corr = __expf(m - nm);
            float p = __expf(s - nm);
            l = l * corr + p;
            a0 = a0 * corr + p * sV[j][lane];
            a1 = a1 * corr + p * sV[j][lane + 32];
            m = nm;
        }
        __syncthreads();
    }
    float inv = 1.f / l;
    g_h[base + (size_t)qrow * D_ + lane]      = a0 * inv;
    g_h[base + (size_t)qrow * D_ + lane + 32] = a1 * inv;
}

// ---------------- head: [B,D] @ [D,V] + b ----------------
__global__ __launch_bounds__(128)
void head_kernel(const float* __restrict__ hw, const float* __restrict__ hb,
                 float* __restrict__ out) {
    __shared__ float sx[2][D_];
    for (int i = threadIdx.x; i < 2 * D_; i += 128)
        sx[i / D_][i % D_] = g_xf[i];
    __syncthreads();
    int v = blockIdx.x * 128 + threadIdx.x;
    float a0 = 0.f, a1 = 0.f;
    #pragma unroll 8
    for (int d = 0; d < D_; d++) {
        float w = hw[(size_t)d * V_ + v];
        a0 += sx[0][d] * w;
        a1 += sx[1][d] * w;
    }
    out[v]      = a0 + hb[v];
    out[V_ + v] = a1 + hb[v];
}

// ---------------- launch ----------------
extern "C" void kernel_launch(void* const* d_in, const int* in_sizes, int n_in,
                              void* d_out, int out_size) {
    const int*   idx  = (const int*)  d_in[0];
    const float* tok  = (const float*)d_in[1];
    const float* pos  = (const float*)d_in[2];
    const float* ln1w = (const float*)d_in[3];
    const float* ln1b = (const float*)d_in[4];
    const float* qw   = (const float*)d_in[5];
    const float* qb   = (const float*)d_in[6];
    const float* kw   = (const float*)d_in[7];
    const float* kb   = (const float*)d_in[8];
    const float* vw   = (const float*)d_in[9];
    const float* vb   = (const float*)d_in[10];
    const float* ow   = (const float*)d_in[11];
    const float* ob   = (const float*)d_in[12];
    const float* ln2w = (const float*)d_in[13];
    const float* ln2b = (const float*)d_in[14];
    const float* f1w  = (const float*)d_in[15];
    const float* f1b  = (const float*)d_in[16];
    const float* f2w  = (const float*)d_in[17];
    const float* f2b  = (const float*)d_in[18];
    const float* lnfw = (const float*)d_in[19];
    const float* lnfb = (const float*)d_in[20];
    const float* hw   = (const float*)d_in[21];
    const float* hb   = (const float*)d_in[22];
    float* out = (float*)d_out;

    float *px, *ph, *pff;
    cudaGetSymbolAddress((void**)&px,  g_x);
    cudaGetSymbolAddress((void**)&ph,  g_h);
    cudaGetSymbolAddress((void**)&pff, g_ff);

    const int ROWS = B_ * T_;   // 2048

    embed_kernel<<<ROWS, 256>>>(idx, tok, pos);

    dim3 gD(D_ / BN, ROWS / BM);          // 8 x 16
    dim3 gQKV(D_ / BN, ROWS / BM, 3);     // 8 x 16 x 3
    dim3 gF1(FF_ / BN, ROWS / BM);        // 32 x 16
    dim3 gAttn(T_ / 8, H_, B_);           // 128 x 16 x 2

    for (int l = 0; l < L_; l++) {
        const size_t wO = (size_t)l * D_ * D_;
        ln_kernel<<<ROWS, 256>>>(px, ln1w + (size_t)l * D_, ln1b + (size_t)l * D_, ph);
        gemm_qkv_kernel<<<gQKV, 256>>>(qw + wO, kw + wO, vw + wO,
                                       qb + (size_t)l * D_, kb + (size_t)l * D_, vb + (size_t)l * D_);
        attn_kernel<<<gAttn, 256>>>();
        gemm_kernel<<<gD, 256>>>(ph, ow + wO, ob + (size_t)l * D_, px, px, D_, D_, 0, 1);
        ln_kernel<<<ROWS, 256>>>(px, ln2w + (size_t)l * D_, ln2b + (size_t)l * D_, ph);
        gemm_kernel<<<gF1, 256>>>(ph, f1w + (size_t)l * D_ * FF_, f1b + (size_t)l * FF_,
                                  nullptr, pff, FF_, D_, 1, 0);
        gemm_kernel<<<gD, 256>>>(pff, f2w + (size_t)l * FF_ * D_, f2b + (size_t)l * D_,
                                 px, px, D_, FF_, 0, 1);
    }

    lnf_kernel<<<B_, 256>>>(lnfw, lnfb);
    head_kernel<<<V_ / 128, 128>>>(hw, hb, out);
}

// round 5
// speedup vs baseline: 1.1122x; 1.1117x over previous
#include <cuda_runtime.h>
#include <math.h>

#define B_  2
#define T_  1024
#define D_  1024
#define H_  16
#define HD_ 64
#define L_  8
#define FF_ 4096
#define V_  32000
#define EPS_ 1e-5f
#define SCALE_ 0.125f   // 1/sqrt(64)

// ---------------- scratch (no allocs allowed) ----------------
__device__ float g_x [B_*T_*D_];   // residual stream
__device__ float g_h [B_*T_*D_];   // ln output / attn output
__device__ float g_q [B_*T_*D_];
__device__ float g_k [B_*T_*D_];
__device__ float g_v [B_*T_*D_];
__device__ float g_ff[B_*T_*FF_];
__device__ float g_xf[B_*D_];      // final-LN of last token per batch

// ---------------- tf32 helpers ----------------
__device__ __forceinline__ unsigned f2tf(float x) {
    unsigned r; asm("cvt.rna.tf32.f32 %0, %1;" : "=r"(r) : "f"(x)); return r;
}
__device__ __forceinline__ void split_tf32(float v, float& hi, float& lo) {
    unsigned h = f2tf(v);
    hi = __uint_as_float(h);
    lo = __uint_as_float(f2tf(v - hi));
}
__device__ __forceinline__ void mma_tf32(float* c, const unsigned* a, const unsigned* b) {
    asm volatile("mma.sync.aligned.m16n8k8.row.col.f32.tf32.tf32.f32 "
        "{%0,%1,%2,%3}, {%4,%5,%6,%7}, {%8,%9}, {%0,%1,%2,%3};"
        : "+f"(c[0]), "+f"(c[1]), "+f"(c[2]), "+f"(c[3])
        : "r"(a[0]), "r"(a[1]), "r"(a[2]), "r"(a[3]), "r"(b[0]), "r"(b[1]));
}

// ---------------- embedding ----------------
__global__ __launch_bounds__(256)
void embed_kernel(const int* __restrict__ idx,
                  const float* __restrict__ tok,
                  const float* __restrict__ pos) {
    int row = blockIdx.x;              // b*T + t
    int t = row & (T_ - 1);
    int tokid = idx[row];
    const float4* te = (const float4*)(tok + (size_t)tokid * D_);
    const float4* pe = (const float4*)(pos + (size_t)t * D_);
    float4* out = (float4*)(g_x + (size_t)row * D_);
    int i = threadIdx.x;               // 256 threads = D/4
    float4 a = te[i], b = pe[i];
    out[i] = make_float4(a.x + b.x, a.y + b.y, a.z + b.z, a.w + b.w);
}

// ---------------- layernorm (vectorized) ----------------
__device__ __forceinline__ void ln_row4(const float* __restrict__ xin,
                                        const float* __restrict__ w,
                                        const float* __restrict__ b,
                                        float* __restrict__ out) {
    __shared__ float red[8], red2[8];
    int tid = threadIdx.x;
    float4 v = ((const float4*)xin)[tid];
    float s = v.x + v.y + v.z + v.w;
    #pragma unroll
    for (int off = 16; off; off >>= 1) s += __shfl_xor_sync(0xffffffffu, s, off);
    if ((tid & 31) == 0) red[tid >> 5] = s;
    __syncthreads();
    float mean = (red[0]+red[1]+red[2]+red[3]+red[4]+red[5]+red[6]+red[7]) * (1.f / D_);
    float dx = v.x - mean, dy = v.y - mean, dz = v.z - mean, dw = v.w - mean;
    float s2 = dx*dx + dy*dy + dz*dz + dw*dw;
    #pragma unroll
    for (int off = 16; off; off >>= 1) s2 += __shfl_xor_sync(0xffffffffu, s2, off);
    if ((tid & 31) == 0) red2[tid >> 5] = s2;
    __syncthreads();
    float var = (red2[0]+red2[1]+red2[2]+red2[3]+red2[4]+red2[5]+red2[6]+red2[7]) * (1.f / D_);
    float rstd = rsqrtf(var + EPS_);
    float4 wv = ((const float4*)w)[tid];
    float4 bv = ((const float4*)b)[tid];
    ((float4*)out)[tid] = make_float4(dx*rstd*wv.x + bv.x, dy*rstd*wv.y + bv.y,
                                      dz*rstd*wv.z + bv.z, dw*rstd*wv.w + bv.w);
}

__global__ __launch_bounds__(256)
void ln_kernel(const float* __restrict__ in, const float* __restrict__ w,
               const float* __restrict__ b, float* __restrict__ out) {
    ln_row4(in + (size_t)blockIdx.x * D_, w, b, out + (size_t)blockIdx.x * D_);
}

__global__ __launch_bounds__(256)
void lnf_kernel(const float* __restrict__ w, const float* __restrict__ b) {
    const float* in = g_x + ((size_t)blockIdx.x * T_ + (T_ - 1)) * D_;
    ln_row4(in, w, b, g_xf + (size_t)blockIdx.x * D_);
}

// ---------------- 3xTF32 tensor-core GEMM ----------------
// C[M,N] = A[M,K] @ B[K,N] (+bias)(relu?)(+res?)
// Block tile 128x64, BK=32, 256 threads = 8 warps (4x2), warp tile 32x32.
#define MBM 128
#define MBN 64
#define MBK 32

__device__ __forceinline__ void mma_gemm_core(
    const float* __restrict__ A, const float* __restrict__ Bw,
    const float* __restrict__ bias, const float* __restrict__ res,
    float* __restrict__ C, int N, int K, int doRelu, int addRes,
    int bx, int by)
{
    __shared__ float sAh[MBK][MBM];   // A^T (k-major), XOR-swizzled on m
    __shared__ float sAl[MBK][MBM];
    __shared__ float sBh[MBK][MBN];   // B (k-major), XOR-swizzled on n
    __shared__ float sBl[MBK][MBN];

    const int tid  = threadIdx.x;
    const int lane = tid & 31;
    const int warp = tid >> 5;
    const int wm = warp >> 1;          // 0..3
    const int wn = warp & 1;           // 0..1
    const int g  = lane >> 2;          // groupID 0..7
    const int tg = lane & 3;           // 0..3

    // gmem staging coords
    const int aR = tid >> 3;           // 0..31
    const int aC = (tid & 7) * 4;      // k 0..28
    const int bR = tid >> 4;           // 0..15
    const int bC = (tid & 15) * 4;     // n 0..60

    const float* Ag = A  + (size_t)(by * MBM + aR) * K + aC;
    const float* Bg = Bw + (size_t)bR * N + (size_t)bx * MBN + bC;

    float acc[2][4][4];
    #pragma unroll
    for (int i = 0; i < 2; i++)
        #pragma unroll
        for (int j = 0; j < 4; j++)
            #pragma unroll
            for (int q = 0; q < 4; q++) acc[i][j][q] = 0.f;

    float4 pa[4], pb[2];
    #pragma unroll
    for (int p = 0; p < 4; p++) pa[p] = *(const float4*)(Ag + (size_t)(p * 32) * K);
    #pragma unroll
    for (int p = 0; p < 2; p++) pb[p] = *(const float4*)(Bg + (size_t)(p * 16) * N);

    const int nc = K / MBK;
    for (int c = 0; c < nc; c++) {
        // ---- store staged chunk to smem, splitting into tf32 hi/lo ----
        #pragma unroll
        for (int p = 0; p < 4; p++) {
            float vv[4] = {pa[p].x, pa[p].y, pa[p].z, pa[p].w};
            int m = p * 32 + aR;
            #pragma unroll
            for (int i = 0; i < 4; i++) {            // k class = i (aC mult of 4)
                float hi, lo; split_tf32(vv[i], hi, lo);
                int mm = m ^ (i * 8);
                sAh[aC + i][mm] = hi;
                sAl[aC + i][mm] = lo;
            }
        }
        #pragma unroll
        for (int p = 0; p < 2; p++) {
            int k = p * 16 + bR;
            int sw = (k & 3) * 8;
            float4 h4, l4;
            split_tf32(pb[p].x, h4.x, l4.x);
            split_tf32(pb[p].y, h4.y, l4.y);
            split_tf32(pb[p].z, h4.z, l4.z);
            split_tf32(pb[p].w, h4.w, l4.w);
            *(float4*)&sBh[k][bC ^ sw] = h4;
            *(float4*)&sBl[k][bC ^ sw] = l4;
        }
        __syncthreads();

        // ---- prefetch next chunk ----
        if (c + 1 < nc) {
            #pragma unroll
            for (int p = 0; p < 4; p++)
                pa[p] = *(const float4*)(Ag + (size_t)(p * 32) * K + (c + 1) * MBK);
            #pragma unroll
            for (int p = 0; p < 2; p++)
                pb[p] = *(const float4*)(Bg + ((size_t)(c + 1) * MBK + p * 16) * N);
        }

        // ---- compute ----
        #pragma unroll
        for (int ks = 0; ks < 4; ks++) {
            const int k0 = ks * 8 + tg;        // and k0+4; both have (k&3)==tg
            const int sw = tg * 8;
            unsigned afh[2][4], afl[2][4], bfh[4][2], bfl[4][2];
            #pragma unroll
            for (int mt = 0; mt < 2; mt++) {
                int m0 = wm * 32 + mt * 16;
                int i0 = (m0 + g) ^ sw;
                int i1 = (m0 + 8 + g) ^ sw;
                afh[mt][0] = __float_as_uint(sAh[k0][i0]);
                afh[mt][1] = __float_as_uint(sAh[k0][i1]);
                afh[mt][2] = __float_as_uint(sAh[k0 + 4][i0]);
                afh[mt][3] = __float_as_uint(sAh[k0 + 4][i1]);
                afl[mt][0] = __float_as_uint(sAl[k0][i0]);
                afl[mt][1] = __float_as_uint(sAl[k0][i1]);
                afl[mt][2] = __float_as_uint(sAl[k0 + 4][i0]);
                afl[mt][3] = __float_as_uint(sAl[k0 + 4][i1]);
            }
            #pragma unroll
            for (int nt = 0; nt < 4; nt++) {
                int j = (wn * 32 + nt * 8 + g) ^ sw;
                bfh[nt][0] = __float_as_uint(sBh[k0][j]);
                bfh[nt][1] = __float_as_uint(sBh[k0 + 4][j]);
                bfl[nt][0] = __float_as_uint(sBl[k0][j]);
                bfl[nt][1] = __float_as_uint(sBl[k0 + 4][j]);
            }
            #pragma unroll
            for (int mt = 0; mt < 2; mt++)
                #pragma unroll
                for (int nt = 0; nt < 4; nt++) {
                    mma_tf32(acc[mt][nt], afh[mt], bfh[nt]);
                    mma_tf32(acc[mt][nt], afh[mt], bfl[nt]);
                    mma_tf32(acc[mt][nt], afl[mt], bfh[nt]);
                }
        }
        __syncthreads();
    }

    // ---- epilogue ----
    #pragma unroll
    for (int mt = 0; mt < 2; mt++) {
        int r0 = by * MBM + wm * 32 + mt * 16 + g;
        #pragma unroll
        for (int nt = 0; nt < 4; nt++) {
            int col = bx * MBN + wn * 32 + nt * 8 + tg * 2;
            float b0v = bias[col], b1v = bias[col + 1];
            float o00 = acc[mt][nt][0] + b0v;
            float o01 = acc[mt][nt][1] + b1v;
            float o10 = acc[mt][nt][2] + b0v;
            float o11 = acc[mt][nt][3] + b1v;
            if (doRelu) {
                o00 = fmaxf(o00, 0.f); o01 = fmaxf(o01, 0.f);
                o10 = fmaxf(o10, 0.f); o11 = fmaxf(o11, 0.f);
            }
            if (addRes) {
                o00 += res[(size_t)r0 * N + col];
                o01 += res[(size_t)r0 * N + col + 1];
                o10 += res[(size_t)(r0 + 8) * N + col];
                o11 += res[(size_t)(r0 + 8) * N + col + 1];
            }
            *(float2*)(C + (size_t)r0 * N + col)       = make_float2(o00, o01);
            *(float2*)(C + (size_t)(r0 + 8) * N + col) = make_float2(o10, o11);
        }
    }
}

__global__ __launch_bounds__(256)
void mma_gemm_kernel(const float* __restrict__ A, const float* __restrict__ Bw,
                     const float* __restrict__ bias, const float* __restrict__ res,
                     float* __restrict__ C, int N, int K, int doRelu, int addRes) {
    mma_gemm_core(A, Bw, bias, res, C, N, K, doRelu, addRes, blockIdx.x, blockIdx.y);
}

__global__ __launch_bounds__(256)
void mma_qkv_kernel(const float* __restrict__ qw, const float* __restrict__ kw,
                    const float* __restrict__ vw, const float* __restrict__ qb,
                    const float* __restrict__ kb, const float* __restrict__ vb) {
    int z = blockIdx.z;
    const float* Bw   = (z == 0) ? qw : (z == 1) ? kw : vw;
    const float* bias = (z == 0) ? qb : (z == 1) ? kb : vb;
    float* Cd         = (z == 0) ? g_q : (z == 1) ? g_k : g_v;
    mma_gemm_core(g_h, Bw, bias, nullptr, Cd, D_, D_, 0, 0, blockIdx.x, blockIdx.y);
}

// ---------------- flash attention: lane-per-key ----------------
__global__ __launch_bounds__(256)
void attn_kernel() {
    __shared__ float sKt[64][33];   // [d][key], padded
    __shared__ float sV[32][64];    // [key][d]
    __shared__ float sQ[8][64];
    __shared__ float sP[8][32];

    const int warp = threadIdx.x >> 5;
    const int lane = threadIdx.x & 31;
    const int qrow = blockIdx.x * 8 + warp;
    const int h = blockIdx.y, b = blockIdx.z;
    const size_t base = (size_t)b * T_ * D_ + (size_t)h * HD_;

    const float* Qp = g_q + base + (size_t)qrow * D_;
    sQ[warp][lane]      = Qp[lane] * SCALE_;
    sQ[warp][lane + 32] = Qp[lane + 32] * SCALE_;

    float m = -1e30f, l = 0.f, a0 = 0.f, a1 = 0.f;
    const int ntiles = (blockIdx.x * 8 + 7) / 32 + 1;

    for (int t = 0; t < ntiles; t++) {
        __syncthreads();   // previous tile consumed (and sQ visible on t=0)
        for (int i = threadIdx.x; i < 32 * 64; i += 256) {
            int r = i >> 6, c2 = i & 63;
            size_t gidx = base + (size_t)(t * 32 + r) * D_ + c2;
            sKt[c2][r] = g_k[gidx];
            sV[r][c2]  = g_v[gidx];
        }
        __syncthreads();

        // score for key = t*32 + lane
        float s = 0.f;
        const float4* q4 = (const float4*)sQ[warp];
        #pragma unroll
        for (int d4 = 0; d4 < 16; d4++) {
            float4 qv = q4[d4];
            s += qv.x * sKt[d4 * 4 + 0][lane];
            s += qv.y * sKt[d4 * 4 + 1][lane];
            s += qv.z * sKt[d4 * 4 + 2][lane];
            s += qv.w * sKt[d4 * 4 + 3][lane];
        }
        if (t * 32 + lane > qrow) s = -1e30f;

        // tile-level online softmax
        float tmax = s;
        #pragma unroll
        for (int off = 16; off; off >>= 1)
            tmax = fmaxf(tmax, __shfl_xor_sync(0xffffffffu, tmax, off));
        float nm = fmaxf(m, tmax);
        float corr = __expf(m - nm);
        float p = __expf(s - nm);
        float ps = p;
        #pragma unroll
        for (int off = 16; off; off >>= 1)
            ps += __shfl_xor_sync(0xffffffffu, ps, off);
        l = l * corr + ps;
        a0 *= corr; a1 *= corr;
        m = nm;

        sP[warp][lane] = p;
        __syncwarp();
        const float4* p4 = (const float4*)sP[warp];
        #pragma unroll
        for (int j4 = 0; j4 < 8; j4++) {
            float4 pv = p4[j4];
            int j = j4 * 4;
            a0 += pv.x * sV[j + 0][lane];  a1 += pv.x * sV[j + 0][lane + 32];
            a0 += pv.y * sV[j + 1][lane];  a1 += pv.y * sV[j + 1][lane + 32];
            a0 += pv.z * sV[j + 2][lane];  a1 += pv.z * sV[j + 2][lane + 32];
            a0 += pv.w * sV[j + 3][lane];  a1 += pv.w * sV[j + 3][lane + 32];
        }
    }
    float inv = 1.f / l;
    g_h[base + (size_t)qrow * D_ + lane]      = a0 * inv;
    g_h[base + (size_t)qrow * D_ + lane + 32] = a1 * inv;
}

// ---------------- head: [B,D] @ [D,V] + b ----------------
__global__ __launch_bounds__(128)
void head_kernel(const float* __restrict__ hw, const float* __restrict__ hb,
                 float* __restrict__ out) {
    __shared__ float sx[2][D_];
    for (int i = threadIdx.x; i < 2 * D_; i += 128)
        sx[i / D_][i % D_] = g_xf[i];
    __syncthreads();
    int v = blockIdx.x * 128 + threadIdx.x;
    float a0 = 0.f, a1 = 0.f;
    #pragma unroll 8
    for (int d = 0; d < D_; d++) {
        float w = hw[(size_t)d * V_ + v];
        a0 += sx[0][d] * w;
        a1 += sx[1][d] * w;
    }
    out[v]      = a0 + hb[v];
    out[V_ + v] = a1 + hb[v];
}

// ---------------- launch ----------------
extern "C" void kernel_launch(void* const* d_in, const int* in_sizes, int n_in,
                              void* d_out, int out_size) {
    const int*   idx  = (const int*)  d_in[0];
    const float* tok  = (const float*)d_in[1];
    const float* pos  = (const float*)d_in[2];
    const float* ln1w = (const float*)d_in[3];
    const float* ln1b = (const float*)d_in[4];
    const float* qw   = (const float*)d_in[5];
    const float* qb   = (const float*)d_in[6];
    const float* kw   = (const float*)d_in[7];
    const float* kb   = (const float*)d_in[8];
    const float* vw   = (const float*)d_in[9];
    const float* vb   = (const float*)d_in[10];
    const float* ow   = (const float*)d_in[11];
    const float* ob   = (const float*)d_in[12];
    const float* ln2w = (const float*)d_in[13];
    const float* ln2b = (const float*)d_in[14];
    const float* f1w  = (const float*)d_in[15];
    const float* f1b  = (const float*)d_in[16];
    const float* f2w  = (const float*)d_in[17];
    const float* f2b  = (const float*)d_in[18];
    const float* lnfw = (const float*)d_in[19];
    const float* lnfb = (const float*)d_in[20];
    const float* hw   = (const float*)d_in[21];
    const float* hb   = (const float*)d_in[22];
    float* out = (float*)d_out;

    float *px, *ph, *pff;
    cudaGetSymbolAddress((void**)&px,  g_x);
    cudaGetSymbolAddress((void**)&ph,  g_h);
    cudaGetSymbolAddress((void**)&pff, g_ff);

    const int ROWS = B_ * T_;   // 2048

    embed_kernel<<<ROWS, 256>>>(idx, tok, pos);

    dim3 gD(D_ / MBN, ROWS / MBM);          // 16 x 16
    dim3 gQKV(D_ / MBN, ROWS / MBM, 3);     // 16 x 16 x 3
    dim3 gF1(FF_ / MBN, ROWS / MBM);        // 64 x 16
    dim3 gAttn(T_ / 8, H_, B_);             // 128 x 16 x 2

    for (int l = 0; l < L_; l++) {
        const size_t wO = (size_t)l * D_ * D_;
        ln_kernel<<<ROWS, 256>>>(px, ln1w + (size_t)l * D_, ln1b + (size_t)l * D_, ph);
        mma_qkv_kernel<<<gQKV, 256>>>(qw + wO, kw + wO, vw + wO,
                                      qb + (size_t)l * D_, kb + (size_t)l * D_, vb + (size_t)l * D_);
        attn_kernel<<<gAttn, 256>>>();
        mma_gemm_kernel<<<gD, 256>>>(ph, ow + wO, ob + (size_t)l * D_, px, px, D_, D_, 0, 1);
        ln_kernel<<<ROWS, 256>>>(px, ln2w + (size_t)l * D_, ln2b + (size_t)l * D_, ph);
        mma_gemm_kernel<<<gF1, 256>>>(ph, f1w + (size_t)l * D_ * FF_, f1b + (size_t)l * FF_,
                                      nullptr, pff, FF_, D_, 1, 0);
        mma_gemm_kernel<<<gD, 256>>>(pff, f2w + (size_t)l * FF_ * D_, f2b + (size_t)l * D_,
                                     px, px, D_, FF_, 0, 1);
    }

    lnf_kernel<<<B_, 256>>>(lnfw, lnfb);
    head_kernel<<<V_ / 128, 128>>>(hw, hb, out);
}

// round 6
// speedup vs baseline: 1.1126x; 1.0003x over previous
#include <cuda_runtime.h>
#include <math.h>

#define B_  2
#define T_  1024
#define D_  1024
#define H_  16
#define HD_ 64
#define L_  8
#define FF_ 4096
#define V_  32000
#define EPS_ 1e-5f
#define SCALE_ 0.125f   // 1/sqrt(64)

// ---------------- scratch (no allocs allowed) ----------------
__device__ float g_x [B_*T_*D_];   // residual stream
__device__ float g_h [B_*T_*D_];   // ln output / attn output
__device__ float g_q [B_*T_*D_];
__device__ float g_k [B_*T_*D_];
__device__ float g_v [B_*T_*D_];
__device__ float g_ff[B_*T_*FF_];
__device__ float g_xf[B_*D_];      // final-LN of last token per batch

// ---------------- tf32 helpers ----------------
__device__ __forceinline__ unsigned f2tf(float x) {
    unsigned r; asm("cvt.rna.tf32.f32 %0, %1;" : "=r"(r) : "f"(x)); return r;
}
__device__ __forceinline__ void split_tf32(float v, float& hi, float& lo) {
    unsigned h = f2tf(v);
    hi = __uint_as_float(h);
    lo = __uint_as_float(f2tf(v - hi));
}
__device__ __forceinline__ void mma_tf32(float* c, const unsigned* a, const unsigned* b) {
    asm volatile("mma.sync.aligned.m16n8k8.row.col.f32.tf32.tf32.f32 "
        "{%0,%1,%2,%3}, {%4,%5,%6,%7}, {%8,%9}, {%0,%1,%2,%3};"
        : "+f"(c[0]), "+f"(c[1]), "+f"(c[2]), "+f"(c[3])
        : "r"(a[0]), "r"(a[1]), "r"(a[2]), "r"(a[3]), "r"(b[0]), "r"(b[1]));
}

// ---------------- embedding ----------------
__global__ __launch_bounds__(256)
void embed_kernel(const int* __restrict__ idx,
                  const float* __restrict__ tok,
                  const float* __restrict__ pos) {
    int row = blockIdx.x;              // b*T + t
    int t = row & (T_ - 1);
    int tokid = idx[row];
    const float4* te = (const float4*)(tok + (size_t)tokid * D_);
    const float4* pe = (const float4*)(pos + (size_t)t * D_);
    float4* out = (float4*)(g_x + (size_t)row * D_);
    int i = threadIdx.x;               // 256 threads = D/4
    float4 a = te[i], b = pe[i];
    out[i] = make_float4(a.x + b.x, a.y + b.y, a.z + b.z, a.w + b.w);
}

// ---------------- layernorm (vectorized) ----------------
__device__ __forceinline__ void ln_row4(const float* __restrict__ xin,
                                        const float* __restrict__ w,
                                        const float* __restrict__ b,
                                        float* __restrict__ out) {
    __shared__ float red[8], red2[8];
    int tid = threadIdx.x;
    float4 v = ((const float4*)xin)[tid];
    float s = v.x + v.y + v.z + v.w;
    #pragma unroll
    for (int off = 16; off; off >>= 1) s += __shfl_xor_sync(0xffffffffu, s, off);
    if ((tid & 31) == 0) red[tid >> 5] = s;
    __syncthreads();
    float mean = (red[0]+red[1]+red[2]+red[3]+red[4]+red[5]+red[6]+red[7]) * (1.f / D_);
    float dx = v.x - mean, dy = v.y - mean, dz = v.z - mean, dw = v.w - mean;
    float s2 = dx*dx + dy*dy + dz*dz + dw*dw;
    #pragma unroll
    for (int off = 16; off; off >>= 1) s2 += __shfl_xor_sync(0xffffffffu, s2, off);
    if ((tid & 31) == 0) red2[tid >> 5] = s2;
    __syncthreads();
    float var = (red2[0]+red2[1]+red2[2]+red2[3]+red2[4]+red2[5]+red2[6]+red2[7]) * (1.f / D_);
    float rstd = rsqrtf(var + EPS_);
    float4 wv = ((const float4*)w)[tid];
    float4 bv = ((const float4*)b)[tid];
    ((float4*)out)[tid] = make_float4(dx*rstd*wv.x + bv.x, dy*rstd*wv.y + bv.y,
                                      dz*rstd*wv.z + bv.z, dw*rstd*wv.w + bv.w);
}

__global__ __launch_bounds__(256)
void ln_kernel(const float* __restrict__ in, const float* __restrict__ w,
               const float* __restrict__ b, float* __restrict__ out) {
    ln_row4(in + (size_t)blockIdx.x * D_, w, b, out + (size_t)blockIdx.x * D_);
}

__global__ __launch_bounds__(256)
void lnf_kernel(const float* __restrict__ w, const float* __restrict__ b) {
    const float* in = g_x + ((size_t)blockIdx.x * T_ + (T_ - 1)) * D_;
    ln_row4(in, w, b, g_xf + (size_t)blockIdx.x * D_);
}

// ---------------- 3xTF32 tensor-core GEMM ----------------
// C[M,N] = A[M,K] @ B[K,N] (+bias)(relu?)(+res?)
// Block tile 128x64, BK=32, 256 threads = 8 warps (4x2), warp tile 32x32.
#define MBM 128
#define MBN 64
#define MBK 32

__device__ __forceinline__ void mma_gemm_core(
    const float* __restrict__ A, const float* __restrict__ Bw,
    const float* __restrict__ bias, const float* __restrict__ res,
    float* __restrict__ C, int N, int K, int doRelu, int addRes,
    int bx, int by)
{
    __shared__ float sAh[MBK][MBM];   // A^T (k-major), XOR-swizzled on m
    __shared__ float sAl[MBK][MBM];
    __shared__ float sBh[MBK][MBN];   // B (k-major), XOR-swizzled on n
    __shared__ float sBl[MBK][MBN];

    const int tid  = threadIdx.x;
    const int lane = tid & 31;
    const int warp = tid >> 5;
    const int wm = warp >> 1;          // 0..3
    const int wn = warp & 1;           // 0..1
    const int g  = lane >> 2;          // groupID 0..7
    const int tg = lane & 3;           // 0..3

    // gmem staging coords
    const int aR = tid >> 3;           // 0..31
    const int aC = (tid & 7) * 4;      // k 0..28
    const int bR = tid >> 4;           // 0..15
    const int bC = (tid & 15) * 4;     // n 0..60

    const float* Ag = A  + (size_t)(by * MBM + aR) * K + aC;
    const float* Bg = Bw + (size_t)bR * N + (size_t)bx * MBN + bC;

    float acc[2][4][4];
    #pragma unroll
    for (int i = 0; i < 2; i++)
        #pragma unroll
        for (int j = 0; j < 4; j++)
            #pragma unroll
            for (int q = 0; q < 4; q++) acc[i][j][q] = 0.f;

    float4 pa[4], pb[2];
    #pragma unroll
    for (int p = 0; p < 4; p++) pa[p] = *(const float4*)(Ag + (size_t)(p * 32) * K);
    #pragma unroll
    for (int p = 0; p < 2; p++) pb[p] = *(const float4*)(Bg + (size_t)(p * 16) * N);

    const int nc = K / MBK;
    for (int c = 0; c < nc; c++) {
        // ---- store staged chunk to smem, splitting into tf32 hi/lo ----
        #pragma unroll
        for (int p = 0; p < 4; p++) {
            float vv[4] = {pa[p].x, pa[p].y, pa[p].z, pa[p].w};
            int m = p * 32 + aR;
            #pragma unroll
            for (int i = 0; i < 4; i++) {            // k class = i (aC mult of 4)
                float hi, lo; split_tf32(vv[i], hi, lo);
                int mm = m ^ (i * 8);
                sAh[aC + i][mm] = hi;
                sAl[aC + i][mm] = lo;
            }
        }
        #pragma unroll
        for (int p = 0; p < 2; p++) {
            int k = p * 16 + bR;
            int sw = (k & 3) * 8;
            float4 h4, l4;
            split_tf32(pb[p].x, h4.x, l4.x);
            split_tf32(pb[p].y, h4.y, l4.y);
            split_tf32(pb[p].z, h4.z, l4.z);
            split_tf32(pb[p].w, h4.w, l4.w);
            *(float4*)&sBh[k][bC ^ sw] = h4;
            *(float4*)&sBl[k][bC ^ sw] = l4;
        }
        __syncthreads();

        // ---- prefetch next chunk ----
        if (c + 1 < nc) {
            #pragma unroll
            for (int p = 0; p < 4; p++)
                pa[p] = *(const float4*)(Ag + (size_t)(p * 32) * K + (c + 1) * MBK);
            #pragma unroll
            for (int p = 0; p < 2; p++)
                pb[p] = *(const float4*)(Bg + ((size_t)(c + 1) * MBK + p * 16) * N);
        }

        // ---- compute ----
        #pragma unroll
        for (int ks = 0; ks < 4; ks++) {
            const int k0 = ks * 8 + tg;        // and k0+4; both have (k&3)==tg
            const int sw = tg * 8;
            unsigned afh[2][4], afl[2][4], bfh[4][2], bfl[4][2];
            #pragma unroll
            for (int mt = 0; mt < 2; mt++) {
                int m0 = wm * 32 + mt * 16;
                int i0 = (m0 + g) ^ sw;
                int i1 = (m0 + 8 + g) ^ sw;
                afh[mt][0] = __float_as_uint(sAh[k0][i0]);
                afh[mt][1] = __float_as_uint(sAh[k0][i1]);
                afh[mt][2] = __float_as_uint(sAh[k0 + 4][i0]);
                afh[mt][3] = __float_as_uint(sAh[k0 + 4][i1]);
                afl[mt][0] = __float_as_uint(sAl[k0][i0]);
                afl[mt][1] = __float_as_uint(sAl[k0][i1]);
                afl[mt][2] = __float_as_uint(sAl[k0 + 4][i0]);
                afl[mt][3] = __float_as_uint(sAl[k0 + 4][i1]);
            }
            #pragma unroll
            for (int nt = 0; nt < 4; nt++) {
                int j = (wn * 32 + nt * 8 + g) ^ sw;
                bfh[nt][0] = __float_as_uint(sBh[k0][j]);
                bfh[nt][1] = __float_as_uint(sBh[k0 + 4][j]);
                bfl[nt][0] = __float_as_uint(sBl[k0][j]);
                bfl[nt][1] = __float_as_uint(sBl[k0 + 4][j]);
            }
            #pragma unroll
            for (int mt = 0; mt < 2; mt++)
                #pragma unroll
                for (int nt = 0; nt < 4; nt++) {
                    mma_tf32(acc[mt][nt], afh[mt], bfh[nt]);
                    mma_tf32(acc[mt][nt], afh[mt], bfl[nt]);
                    mma_tf32(acc[mt][nt], afl[mt], bfh[nt]);
                }
        }
        __syncthreads();
    }

    // ---- epilogue ----
    #pragma unroll
    for (int mt = 0; mt < 2; mt++) {
        int r0 = by * MBM + wm * 32 + mt * 16 + g;
        #pragma unroll
        for (int nt = 0; nt < 4; nt++) {
            int col = bx * MBN + wn * 32 + nt * 8 + tg * 2;
            float b0v = bias[col], b1v = bias[col + 1];
            float o00 = acc[mt][nt][0] + b0v;
            float o01 = acc[mt][nt][1] + b1v;
            float o10 = acc[mt][nt][2] + b0v;
            float o11 = acc[mt][nt][3] + b1v;
            if (doRelu) {
                o00 = fmaxf(o00, 0.f); o01 = fmaxf(o01, 0.f);
                o10 = fmaxf(o10, 0.f); o11 = fmaxf(o11, 0.f);
            }
            if (addRes) {
                o00 += res[(size_t)r0 * N + col];
                o01 += res[(size_t)r0 * N + col + 1];
                o10 += res[(size_t)(r0 + 8) * N + col];
                o11 += res[(size_t)(r0 + 8) * N + col + 1];
            }
            *(float2*)(C + (size_t)r0 * N + col)       = make_float2(o00, o01);
            *(float2*)(C + (size_t)(r0 + 8) * N + col) = make_float2(o10, o11);
        }
    }
}

__global__ __launch_bounds__(256)
void mma_gemm_kernel(const float* __restrict__ A, const float* __restrict__ Bw,
                     const float* __restrict__ bias, const float* __restrict__ res,
                     float* __restrict__ C, int N, int K, int doRelu, int addRes) {
    mma_gemm_core(A, Bw, bias, res, C, N, K, doRelu, addRes, blockIdx.x, blockIdx.y);
}

__global__ __launch_bounds__(256)
void mma_qkv_kernel(const float* __restrict__ qw, const float* __restrict__ kw,
                    const float* __restrict__ vw, const float* __restrict__ qb,
                    const float* __restrict__ kb, const float* __restrict__ vb) {
    int z = blockIdx.z;
    const float* Bw   = (z == 0) ? qw : (z == 1) ? kw : vw;
    const float* bias = (z == 0) ? qb : (z == 1) ? kb : vb;
    float* Cd         = (z == 0) ? g_q : (z == 1) ? g_k : g_v;
    mma_gemm_core(g_h, Bw, bias, nullptr, Cd, D_, D_, 0, 0, blockIdx.x, blockIdx.y);
}

// ---------------- flash attention: lane-per-key ----------------
__global__ __launch_bounds__(256)
void attn_kernel() {
    __shared__ float sKt[64][33];   // [d][key], padded
    __shared__ float sV[32][64];    // [key][d]
    __shared__ float sQ[8][64];
    __shared__ float sP[8][32];

    const int warp = threadIdx.x >> 5;
    const int lane = threadIdx.x & 31;
    const int qrow = blockIdx.x * 8 + warp;
    const int h = blockIdx.y, b = blockIdx.z;
    const size_t base = (size_t)b * T_ * D_ + (size_t)h * HD_;

    const float* Qp = g_q + base + (size_t)qrow * D_;
    sQ[warp][lane]      = Qp[lane] * SCALE_;
    sQ[warp][lane + 32] = Qp[lane + 32] * SCALE_;

    float m = -1e30f, l = 0.f, a0 = 0.f, a1 = 0.f;
    const int ntiles = (blockIdx.x * 8 + 7) / 32 + 1;

    for (int t = 0; t < ntiles; t++) {
        __syncthreads();   // previous tile consumed (and sQ visible on t=0)
        for (int i = threadIdx.x; i < 32 * 64; i += 256) {
            int r = i >> 6, c2 = i & 63;
            size_t gidx = base + (size_t)(t * 32 + r) * D_ + c2;
            sKt[c2][r] = g_k[gidx];
            sV[r][c2]  = g_v[gidx];
        }
        __syncthreads();

        // score for key = t*32 + lane
        float s = 0.f;
        const float4* q4 = (const float4*)sQ[warp];
        #pragma unroll
        for (int d4 = 0; d4 < 16; d4++) {
            float4 qv = q4[d4];
            s += qv.x * sKt[d4 * 4 + 0][lane];
            s += qv.y * sKt[d4 * 4 + 1][lane];
            s += qv.z * sKt[d4 * 4 + 2][lane];
            s += qv.w * sKt[d4 * 4 + 3][lane];
        }
        if (t * 32 + lane > qrow) s = -1e30f;

        // tile-level online softmax
        float tmax = s;
        #pragma unroll
        for (int off = 16; off; off >>= 1)
            tmax = fmaxf(tmax, __shfl_xor_sync(0xffffffffu, tmax, off));
        float nm = fmaxf(m, tmax);
        float corr = __expf(m - nm);
        float p = __expf(s - nm);
        float ps = p;
        #pragma unroll
        for (int off = 16; off; off >>= 1)
            ps += __shfl_xor_sync(0xffffffffu, ps, off);
        l = l * corr + ps;
        a0 *= corr; a1 *= corr;
        m = nm;

        sP[warp][lane] = p;
        __syncwarp();
        const float4* p4 = (const float4*)sP[warp];
        #pragma unroll
        for (int j4 = 0; j4 < 8; j4++) {
            float4 pv = p4[j4];
            int j = j4 * 4;
            a0 += pv.x * sV[j + 0][lane];  a1 += pv.x * sV[j + 0][lane + 32];
            a0 += pv.y * sV[j + 1][lane];  a1 += pv.y * sV[j + 1][lane + 32];
            a0 += pv.z * sV[j + 2][lane];  a1 += pv.z * sV[j + 2][lane + 32];
            a0 += pv.w * sV[j + 3][lane];  a1 += pv.w * sV[j + 3][lane + 32];
        }
    }
    float inv = 1.f / l;
    g_h[base + (size_t)qrow * D_ + lane]      = a0 * inv;
    g_h[base + (size_t)qrow * D_ + lane + 32] = a1 * inv;
}

// ---------------- head: [B,D] @ [D,V] + b ----------------
__global__ __launch_bounds__(128)
void head_kernel(const float* __restrict__ hw, const float* __restrict__ hb,
                 float* __restrict__ out) {
    __shared__ float sx[2][D_];
    for (int i = threadIdx.x; i < 2 * D_; i += 128)
        sx[i / D_][i % D_] = g_xf[i];
    __syncthreads();
    int v = blockIdx.x * 128 + threadIdx.x;
    float a0 = 0.f, a1 = 0.f;
    #pragma unroll 8
    for (int d = 0; d < D_; d++) {
        float w = hw[(size_t)d * V_ + v];
        a0 += sx[0][d] * w;
        a1 += sx[1][d] * w;
    }
    out[v]      = a0 + hb[v];
    out[V_ + v] = a1 + hb[v];
}

// ---------------- launch ----------------
extern "C" void kernel_launch(void* const* d_in, const int* in_sizes, int n_in,
                              void* d_out, int out_size) {
    const int*   idx  = (const int*)  d_in[0];
    const float* tok  = (const float*)d_in[1];
    const float* pos  = (const float*)d_in[2];
    const float* ln1w = (const float*)d_in[3];
    const float* ln1b = (const float*)d_in[4];
    const float* qw   = (const float*)d_in[5];
    const float* qb   = (const float*)d_in[6];
    const float* kw   = (const float*)d_in[7];
    const float* kb   = (const float*)d_in[8];
    const float* vw   = (const float*)d_in[9];
    const float* vb   = (const float*)d_in[10];
    const float* ow   = (const float*)d_in[11];
    const float* ob   = (const float*)d_in[12];
    const float* ln2w = (const float*)d_in[13];
    const float* ln2b = (const float*)d_in[14];
    const float* f1w  = (const float*)d_in[15];
    const float* f1b  = (const float*)d_in[16];
    const float* f2w  = (const float*)d_in[17];
    const float* f2b  = (const float*)d_in[18];
    const float* lnfw = (const float*)d_in[19];
    const float* lnfb = (const float*)d_in[20];
    const float* hw   = (const float*)d_in[21];
    const float* hb   = (const float*)d_in[22];
    float* out = (float*)d_out;

    float *px, *ph, *pff;
    cudaGetSymbolAddress((void**)&px,  g_x);
    cudaGetSymbolAddress((void**)&ph,  g_h);
    cudaGetSymbolAddress((void**)&pff, g_ff);

    const int ROWS = B_ * T_;   // 2048

    embed_kernel<<<ROWS, 256>>>(idx, tok, pos);

    dim3 gD(D_ / MBN, ROWS / MBM);          // 16 x 16
    dim3 gQKV(D_ / MBN, ROWS / MBM, 3);     // 16 x 16 x 3
    dim3 gF1(FF_ / MBN, ROWS / MBM);        // 64 x 16
    dim3 gAttn(T_ / 8, H_, B_);             // 128 x 16 x 2

    for (int l = 0; l < L_; l++) {
        const size_t wO = (size_t)l * D_ * D_;
        ln_kernel<<<ROWS, 256>>>(px, ln1w + (size_t)l * D_, ln1b + (size_t)l * D_, ph);
        mma_qkv_kernel<<<gQKV, 256>>>(qw + wO, kw + wO, vw + wO,
                                      qb + (size_t)l * D_, kb + (size_t)l * D_, vb + (size_t)l * D_);
        attn_kernel<<<gAttn, 256>>>();
        mma_gemm_kernel<<<gD, 256>>>(ph, ow + wO, ob + (size_t)l * D_, px, px, D_, D_, 0, 1);
        ln_kernel<<<ROWS, 256>>>(px, ln2w + (size_t)l * D_, ln2b + (size_t)l * D_, ph);
        mma_gemm_kernel<<<gF1, 256>>>(ph, f1w + (size_t)l * D_ * FF_, f1b + (size_t)l * FF_,
                                      nullptr, pff, FF_, D_, 1, 0);
        mma_gemm_kernel<<<gD, 256>>>(pff, f2w + (size_t)l * FF_ * D_, f2b + (size_t)l * D_,
                                     px, px, D_, FF_, 0, 1);
    }

    lnf_kernel<<<B_, 256>>>(lnfw, lnfb);
    head_kernel<<<V_ / 128, 128>>>(hw, hb, out);
}

// round 7
// speedup vs baseline: 1.1135x; 1.0009x over previous
#include <cuda_runtime.h>
#include <math.h>

#define B_  2
#define T_  1024
#define D_  1024
#define H_  16
#define HD_ 64
#define L_  8
#define FF_ 4096
#define V_  32000
#define EPS_ 1e-5f
#define SCALE_ 0.125f   // 1/sqrt(64)

// ---------------- scratch (no allocs allowed) ----------------
__device__ float g_x [B_*T_*D_];   // residual stream
__device__ float g_h [B_*T_*D_];   // ln output / attn output
__device__ float g_q [B_*T_*D_];
__device__ float g_k [B_*T_*D_];
__device__ float g_v [B_*T_*D_];
__device__ float g_ff[B_*T_*FF_];
__device__ float g_xf[B_*D_];      // final-LN of last token per batch

// ---------------- tf32 helpers ----------------
__device__ __forceinline__ unsigned f2tf(float x) {
    unsigned r; asm("cvt.rna.tf32.f32 %0, %1;" : "=r"(r) : "f"(x)); return r;
}
__device__ __forceinline__ void split_tf32(float v, float& hi, float& lo) {
    unsigned h = f2tf(v);
    hi = __uint_as_float(h);
    lo = __uint_as_float(f2tf(v - hi));
}
__device__ __forceinline__ void mma_tf32(float* c, const unsigned* a, const unsigned* b) {
    asm volatile("mma.sync.aligned.m16n8k8.row.col.f32.tf32.tf32.f32 "
        "{%0,%1,%2,%3}, {%4,%5,%6,%7}, {%8,%9}, {%0,%1,%2,%3};"
        : "+f"(c[0]), "+f"(c[1]), "+f"(c[2]), "+f"(c[3])
        : "r"(a[0]), "r"(a[1]), "r"(a[2]), "r"(a[3]), "r"(b[0]), "r"(b[1]));
}

// ---------------- embedding ----------------
__global__ __launch_bounds__(256)
void embed_kernel(const int* __restrict__ idx,
                  const float* __restrict__ tok,
                  const float* __restrict__ pos) {
    int row = blockIdx.x;              // b*T + t
    int t = row & (T_ - 1);
    int tokid = idx[row];
    const float4* te = (const float4*)(tok + (size_t)tokid * D_);
    const float4* pe = (const float4*)(pos + (size_t)t * D_);
    float4* out = (float4*)(g_x + (size_t)row * D_);
    int i = threadIdx.x;               // 256 threads = D/4
    float4 a = te[i], b = pe[i];
    out[i] = make_float4(a.x + b.x, a.y + b.y, a.z + b.z, a.w + b.w);
}

// ---------------- layernorm (vectorized) ----------------
__device__ __forceinline__ void ln_row4(const float* __restrict__ xin,
                                        const float* __restrict__ w,
                                        const float* __restrict__ b,
                                        float* __restrict__ out) {
    __shared__ float red[8], red2[8];
    int tid = threadIdx.x;
    float4 v = ((const float4*)xin)[tid];
    float s = v.x + v.y + v.z + v.w;
    #pragma unroll
    for (int off = 16; off; off >>= 1) s += __shfl_xor_sync(0xffffffffu, s, off);
    if ((tid & 31) == 0) red[tid >> 5] = s;
    __syncthreads();
    float mean = (red[0]+red[1]+red[2]+red[3]+red[4]+red[5]+red[6]+red[7]) * (1.f / D_);
    float dx = v.x - mean, dy = v.y - mean, dz = v.z - mean, dw = v.w - mean;
    float s2 = dx*dx + dy*dy + dz*dz + dw*dw;
    #pragma unroll
    for (int off = 16; off; off >>= 1) s2 += __shfl_xor_sync(0xffffffffu, s2, off);
    if ((tid & 31) == 0) red2[tid >> 5] = s2;
    __syncthreads();
    float var = (red2[0]+red2[1]+red2[2]+red2[3]+red2[4]+red2[5]+red2[6]+red2[7]) * (1.f / D_);
    float rstd = rsqrtf(var + EPS_);
    float4 wv = ((const float4*)w)[tid];
    float4 bv = ((const float4*)b)[tid];
    ((float4*)out)[tid] = make_float4(dx*rstd*wv.x + bv.x, dy*rstd*wv.y + bv.y,
                                      dz*rstd*wv.z + bv.z, dw*rstd*wv.w + bv.w);
}

__global__ __launch_bounds__(256)
void ln_kernel(const float* __restrict__ in, const float* __restrict__ w,
               const float* __restrict__ b, float* __restrict__ out) {
    ln_row4(in + (size_t)blockIdx.x * D_, w, b, out + (size_t)blockIdx.x * D_);
}

__global__ __launch_bounds__(256)
void lnf_kernel(const float* __restrict__ w, const float* __restrict__ b) {
    const float* in = g_x + ((size_t)blockIdx.x * T_ + (T_ - 1)) * D_;
    ln_row4(in, w, b, g_xf + (size_t)blockIdx.x * D_);
}

// ---------------- 3xTF32 tensor-core GEMM ----------------
// C[M,N] = A[M,K] @ B[K,N] (+bias)(relu?)(+res?)
// Block tile 128x64, BK=32, 256 threads = 8 warps (4x2), warp tile 32x32.
#define MBM 128
#define MBN 64
#define MBK 32

__device__ __forceinline__ void mma_gemm_core(
    const float* __restrict__ A, const float* __restrict__ Bw,
    const float* __restrict__ bias, const float* __restrict__ res,
    float* __restrict__ C, int N, int K, int doRelu, int addRes,
    int bx, int by)
{
    __shared__ float sAh[MBK][MBM];   // A^T (k-major), XOR-swizzled on m
    __shared__ float sAl[MBK][MBM];
    __shared__ float sBh[MBK][MBN];   // B (k-major), XOR-swizzled on n
    __shared__ float sBl[MBK][MBN];

    const int tid  = threadIdx.x;
    const int lane = tid & 31;
    const int warp = tid >> 5;
    const int wm = warp >> 1;          // 0..3
    const int wn = warp & 1;           // 0..1
    const int g  = lane >> 2;          // groupID 0..7
    const int tg = lane & 3;           // 0..3

    // gmem staging coords
    const int aR = tid >> 3;           // 0..31
    const int aC = (tid & 7) * 4;      // k 0..28
    const int bR = tid >> 4;           // 0..15
    const int bC = (tid & 15) * 4;     // n 0..60

    const float* Ag = A  + (size_t)(by * MBM + aR) * K + aC;
    const float* Bg = Bw + (size_t)bR * N + (size_t)bx * MBN + bC;

    float acc[2][4][4];
    #pragma unroll
    for (int i = 0; i < 2; i++)
        #pragma unroll
        for (int j = 0; j < 4; j++)
            #pragma unroll
            for (int q = 0; q < 4; q++) acc[i][j][q] = 0.f;

    float4 pa[4], pb[2];
    #pragma unroll
    for (int p = 0; p < 4; p++) pa[p] = *(const float4*)(Ag + (size_t)(p * 32) * K);
    #pragma unroll
    for (int p = 0; p < 2; p++) pb[p] = *(const float4*)(Bg + (size_t)(p * 16) * N);

    const int nc = K / MBK;
    for (int c = 0; c < nc; c++) {
        // ---- store staged chunk to smem, splitting into tf32 hi/lo ----
        #pragma unroll
        for (int p = 0; p < 4; p++) {
            float vv[4] = {pa[p].x, pa[p].y, pa[p].z, pa[p].w};
            int m = p * 32 + aR;
            #pragma unroll
            for (int i = 0; i < 4; i++) {            // k class = i (aC mult of 4)
                float hi, lo; split_tf32(vv[i], hi, lo);
                int mm = m ^ (i * 8);
                sAh[aC + i][mm] = hi;
                sAl[aC + i][mm] = lo;
            }
        }
        #pragma unroll
        for (int p = 0; p < 2; p++) {
            int k = p * 16 + bR;
            int sw = (k & 3) * 8;
            float4 h4, l4;
            split_tf32(pb[p].x, h4.x, l4.x);
            split_tf32(pb[p].y, h4.y, l4.y);
            split_tf32(pb[p].z, h4.z, l4.z);
            split_tf32(pb[p].w, h4.w, l4.w);
            *(float4*)&sBh[k][bC ^ sw] = h4;
            *(float4*)&sBl[k][bC ^ sw] = l4;
        }
        __syncthreads();

        // ---- prefetch next chunk ----
        if (c + 1 < nc) {
            #pragma unroll
            for (int p = 0; p < 4; p++)
                pa[p] = *(const float4*)(Ag + (size_t)(p * 32) * K + (c + 1) * MBK);
            #pragma unroll
            for (int p = 0; p < 2; p++)
                pb[p] = *(const float4*)(Bg + ((size_t)(c + 1) * MBK + p * 16) * N);
        }

        // ---- compute ----
        #pragma unroll
        for (int ks = 0; ks < 4; ks++) {
            const int k0 = ks * 8 + tg;        // and k0+4; both have (k&3)==tg
            const int sw = tg * 8;
            unsigned afh[2][4], afl[2][4], bfh[4][2], bfl[4][2];
            #pragma unroll
            for (int mt = 0; mt < 2; mt++) {
                int m0 = wm * 32 + mt * 16;
                int i0 = (m0 + g) ^ sw;
                int i1 = (m0 + 8 + g) ^ sw;
                afh[mt][0] = __float_as_uint(sAh[k0][i0]);
                afh[mt][1] = __float_as_uint(sAh[k0][i1]);
                afh[mt][2] = __float_as_uint(sAh[k0 + 4][i0]);
                afh[mt][3] = __float_as_uint(sAh[k0 + 4][i1]);
                afl[mt][0] = __float_as_uint(sAl[k0][i0]);
                afl[mt][1] = __float_as_uint(sAl[k0][i1]);
                afl[mt][2] = __float_as_uint(sAl[k0 + 4][i0]);
                afl[mt][3] = __float_as_uint(sAl[k0 + 4][i1]);
            }
            #pragma unroll
            for (int nt = 0; nt < 4; nt++) {
                int j = (wn * 32 + nt * 8 + g) ^ sw;
                bfh[nt][0] = __float_as_uint(sBh[k0][j]);
                bfh[nt][1] = __float_as_uint(sBh[k0 + 4][j]);
                bfl[nt][0] = __float_as_uint(sBl[k0][j]);
                bfl[nt][1] = __float_as_uint(sBl[k0 + 4][j]);
            }
            #pragma unroll
            for (int mt = 0; mt < 2; mt++)
                #pragma unroll
                for (int nt = 0; nt < 4; nt++) {
                    mma_tf32(acc[mt][nt], afh[mt], bfh[nt]);
                    mma_tf32(acc[mt][nt], afh[mt], bfl[nt]);
                    mma_tf32(acc[mt][nt], afl[mt], bfh[nt]);
                }
        }
        __syncthreads();
    }

    // ---- epilogue ----
    #pragma unroll
    for (int mt = 0; mt < 2; mt++) {
        int r0 = by * MBM + wm * 32 + mt * 16 + g;
        #pragma unroll
        for (int nt = 0; nt < 4; nt++) {
            int col = bx * MBN + wn * 32 + nt * 8 + tg * 2;
            float b0v = bias[col], b1v = bias[col + 1];
            float o00 = acc[mt][nt][0] + b0v;
            float o01 = acc[mt][nt][1] + b1v;
            float o10 = acc[mt][nt][2] + b0v;
            float o11 = acc[mt][nt][3] + b1v;
            if (doRelu) {
                o00 = fmaxf(o00, 0.f); o01 = fmaxf(o01, 0.f);
                o10 = fmaxf(o10, 0.f); o11 = fmaxf(o11, 0.f);
            }
            if (addRes) {
                o00 += res[(size_t)r0 * N + col];
                o01 += res[(size_t)r0 * N + col + 1];
                o10 += res[(size_t)(r0 + 8) * N + col];
                o11 += res[(size_t)(r0 + 8) * N + col + 1];
            }
            *(float2*)(C + (size_t)r0 * N + col)       = make_float2(o00, o01);
            *(float2*)(C + (size_t)(r0 + 8) * N + col) = make_float2(o10, o11);
        }
    }
}

__global__ __launch_bounds__(256)
void mma_gemm_kernel(const float* __restrict__ A, const float* __restrict__ Bw,
                     const float* __restrict__ bias, const float* __restrict__ res,
                     float* __restrict__ C, int N, int K, int doRelu, int addRes) {
    mma_gemm_core(A, Bw, bias, res, C, N, K, doRelu, addRes, blockIdx.x, blockIdx.y);
}

__global__ __launch_bounds__(256)
void mma_qkv_kernel(const float* __restrict__ qw, const float* __restrict__ kw,
                    const float* __restrict__ vw, const float* __restrict__ qb,
                    const float* __restrict__ kb, const float* __restrict__ vb) {
    int z = blockIdx.z;
    const float* Bw   = (z == 0) ? qw : (z == 1) ? kw : vw;
    const float* bias = (z == 0) ? qb : (z == 1) ? kb : vb;
    float* Cd         = (z == 0) ? g_q : (z == 1) ? g_k : g_v;
    mma_gemm_core(g_h, Bw, bias, nullptr, Cd, D_, D_, 0, 0, blockIdx.x, blockIdx.y);
}

// ---------------- flash attention: lane-per-key ----------------
__global__ __launch_bounds__(256)
void attn_kernel() {
    __shared__ float sKt[64][33];   // [d][key], padded
    __shared__ float sV[32][64];    // [key][d]
    __shared__ float sQ[8][64];
    __shared__ float sP[8][32];

    const int warp = threadIdx.x >> 5;
    const int lane = threadIdx.x & 31;
    const int qrow = blockIdx.x * 8 + warp;
    const int h = blockIdx.y, b = blockIdx.z;
    const size_t base = (size_t)b * T_ * D_ + (size_t)h * HD_;

    const float* Qp = g_q + base + (size_t)qrow * D_;
    sQ[warp][lane]      = Qp[lane] * SCALE_;
    sQ[warp][lane + 32] = Qp[lane + 32] * SCALE_;

    float m = -1e30f, l = 0.f, a0 = 0.f, a1 = 0.f;
    const int ntiles = (blockIdx.x * 8 + 7) / 32 + 1;

    for (int t = 0; t < ntiles; t++) {
        __syncthreads();   // previous tile consumed (and sQ visible on t=0)
        for (int i = threadIdx.x; i < 32 * 64; i += 256) {
            int r = i >> 6, c2 = i & 63;
            size_t gidx = base + (size_t)(t * 32 + r) * D_ + c2;
            sKt[c2][r] = g_k[gidx];
            sV[r][c2]  = g_v[gidx];
        }
        __syncthreads();

        // score for key = t*32 + lane
        float s = 0.f;
        const float4* q4 = (const float4*)sQ[warp];
        #pragma unroll
        for (int d4 = 0; d4 < 16; d4++) {
            float4 qv = q4[d4];
            s += qv.x * sKt[d4 * 4 + 0][lane];
            s += qv.y * sKt[d4 * 4 + 1][lane];
            s += qv.z * sKt[d4 * 4 + 2][lane];
            s += qv.w * sKt[d4 * 4 + 3][lane];
        }
        if (t * 32 + lane > qrow) s = -1e30f;

        // tile-level online softmax
        float tmax = s;
        #pragma unroll
        for (int off = 16; off; off >>= 1)
            tmax = fmaxf(tmax, __shfl_xor_sync(0xffffffffu, tmax, off));
        float nm = fmaxf(m, tmax);
        float corr = __expf(m - nm);
        float p = __expf(s - nm);
        float ps = p;
        #pragma unroll
        for (int off = 16; off; off >>= 1)
            ps += __shfl_xor_sync(0xffffffffu, ps, off);
        l = l * corr + ps;
        a0 *= corr; a1 *= corr;
        m = nm;

        sP[warp][lane] = p;
        __syncwarp();
        const float4* p4 = (const float4*)sP[warp];
        #pragma unroll
        for (int j4 = 0; j4 < 8; j4++) {
            float4 pv = p4[j4];
            int j = j4 * 4;
            a0 += pv.x * sV[j + 0][lane];  a1 += pv.x * sV[j + 0][lane + 32];
            a0 += pv.y * sV[j + 1][lane];  a1 += pv.y * sV[j + 1][lane + 32];
            a0 += pv.z * sV[j + 2][lane];  a1 += pv.z * sV[j + 2][lane + 32];
            a0 += pv.w * sV[j + 3][lane];  a1 += pv.w * sV[j + 3][lane + 32];
        }
    }
    float inv = 1.f / l;
    g_h[base + (size_t)qrow * D_ + lane]      = a0 * inv;
    g_h[base + (size_t)qrow * D_ + lane + 32] = a1 * inv;
}

// ---------------- head: [B,D] @ [D,V] + b ----------------
__global__ __launch_bounds__(128)
void head_kernel(const float* __restrict__ hw, const float* __restrict__ hb,
                 float* __restrict__ out) {
    __shared__ float sx[2][D_];
    for (int i = threadIdx.x; i < 2 * D_; i += 128)
        sx[i / D_][i % D_] = g_xf[i];
    __syncthreads();
    int v = blockIdx.x * 128 + threadIdx.x;
    float a0 = 0.f, a1 = 0.f;
    #pragma unroll 8
    for (int d = 0; d < D_; d++) {
        float w = hw[(size_t)d * V_ + v];
        a0 += sx[0][d] * w;
        a1 += sx[1][d] * w;
    }
    out[v]      = a0 + hb[v];
    out[V_ + v] = a1 + hb[v];
}

// ---------------- launch ----------------
extern "C" void kernel_launch(void* const* d_in, const int* in_sizes, int n_in,
                              void* d_out, int out_size) {
    const int*   idx  = (const int*)  d_in[0];
    const float* tok  = (const float*)d_in[1];
    const float* pos  = (const float*)d_in[2];
    const float* ln1w = (const float*)d_in[3];
    const float* ln1b = (const float*)d_in[4];
    const float* qw   = (const float*)d_in[5];
    const float* qb   = (const float*)d_in[6];
    const float* kw   = (const float*)d_in[7];
    const float* kb   = (const float*)d_in[8];
    const float* vw   = (const float*)d_in[9];
    const float* vb   = (const float*)d_in[10];
    const float* ow   = (const float*)d_in[11];
    const float* ob   = (const float*)d_in[12];
    const float* ln2w = (const float*)d_in[13];
    const float* ln2b = (const float*)d_in[14];
    const float* f1w  = (const float*)d_in[15];
    const float* f1b  = (const float*)d_in[16];
    const float* f2w  = (const float*)d_in[17];
    const float* f2b  = (const float*)d_in[18];
    const float* lnfw = (const float*)d_in[19];
    const float* lnfb = (const float*)d_in[20];
    const float* hw   = (const float*)d_in[21];
    const float* hb   = (const float*)d_in[22];
    float* out = (float*)d_out;

    float *px, *ph, *pff;
    cudaGetSymbolAddress((void**)&px,  g_x);
    cudaGetSymbolAddress((void**)&ph,  g_h);
    cudaGetSymbolAddress((void**)&pff, g_ff);

    const int ROWS = B_ * T_;   // 2048

    embed_kernel<<<ROWS, 256>>>(idx, tok, pos);

    dim3 gD(D_ / MBN, ROWS / MBM);          // 16 x 16
    dim3 gQKV(D_ / MBN, ROWS / MBM, 3);     // 16 x 16 x 3
    dim3 gF1(FF_ / MBN, ROWS / MBM);        // 64 x 16
    dim3 gAttn(T_ / 8, H_, B_);             // 128 x 16 x 2

    for (int l = 0; l < L_; l++) {
        const size_t wO = (size_t)l * D_ * D_;
        ln_kernel<<<ROWS, 256>>>(px, ln1w + (size_t)l * D_, ln1b + (size_t)l * D_, ph);
        mma_qkv_kernel<<<gQKV, 256>>>(qw + wO, kw + wO, vw + wO,
                                      qb + (size_t)l * D_, kb + (size_t)l * D_, vb + (size_t)l * D_);
        attn_kernel<<<gAttn, 256>>>();
        mma_gemm_kernel<<<gD, 256>>>(ph, ow + wO, ob + (size_t)l * D_, px, px, D_, D_, 0, 1);
        ln_kernel<<<ROWS, 256>>>(px, ln2w + (size_t)l * D_, ln2b + (size_t)l * D_, ph);
        mma_gemm_kernel<<<gF1, 256>>>(ph, f1w + (size_t)l * D_ * FF_, f1b + (size_t)l * FF_,
                                      nullptr, pff, FF_, D_, 1, 0);
        mma_gemm_kernel<<<gD, 256>>>(pff, f2w + (size_t)l * FF_ * D_, f2b + (size_t)l * D_,
                                     px, px, D_, FF_, 0, 1);
    }

    lnf_kernel<<<B_, 256>>>(lnfw, lnfb);
    head_kernel<<<V_ / 128, 128>>>(hw, hb, out);
}